// round 13
// baseline (speedup 1.0000x reference)
#include <cuda_runtime.h>
#include <math.h>

// ---------------- problem constants ----------------
#define DIMC   1024
#define B_     4
#define N_     4096
#define T_     256
#define H_     16
#define D_     64
#define INNER_ 1024
#define TK_    257       // T + 1 null token
#define FT_    320       // padded kv storage length
#define ROWS_X (B_*N_)   // 16384
#define ROWS_C (B_*T_)   // 1024

// ---------------- device scratch (static, no allocations) ----------------
__device__ float g_xn[(size_t)ROWS_X*DIMC];
__device__ float g_cn[(size_t)ROWS_C*DIMC];
__device__ float g_q [(size_t)ROWS_X*INNER_];
__device__ float g_kv[(size_t)ROWS_C*2*INNER_];
__device__ float g_k [(size_t)64*FT_*D_];     // normalized, tf32-rounded, [bh][t][d]
__device__ float g_v [(size_t)64*FT_*D_];     // tf32-rounded, [bh][t][d]
__device__ float g_ao[(size_t)ROWS_X*INNER_];
__device__ float g_pr[(size_t)ROWS_X*DIMC];
__device__ float g_w [(size_t)4*1024*1024];   // tf32 weights: Wq[0,1M) Wkv[1M,3M) Wo[3M,4M)

// ---------------- tf32 helpers ----------------
__device__ __forceinline__ unsigned f2tf32(float x) {
    unsigned u;
    asm("cvt.rna.tf32.f32 %0, %1;" : "=r"(u) : "f"(x));
    return u;
}
__device__ __forceinline__ float f2tf32f(float x) { return __uint_as_float(f2tf32(x)); }
__device__ __forceinline__ void mma_tf32(float c[4], const unsigned a[4], const unsigned b[2]) {
    asm volatile(
        "mma.sync.aligned.m16n8k8.row.col.f32.tf32.tf32.f32 "
        "{%0,%1,%2,%3}, {%4,%5,%6,%7}, {%8,%9}, {%0,%1,%2,%3};"
        : "+f"(c[0]), "+f"(c[1]), "+f"(c[2]), "+f"(c[3])
        : "r"(a[0]), "r"(a[1]), "r"(a[2]), "r"(a[3]), "r"(b[0]), "r"(b[1]));
}
__device__ __forceinline__ void cp16(unsigned dst, const void* src) {
    asm volatile("cp.async.cg.shared.global [%0], [%1], 16;\n" :: "r"(dst), "l"(src));
}
__device__ __forceinline__ void cp_commit() { asm volatile("cp.async.commit_group;\n"); }
template<int N> __device__ __forceinline__ void cp_wait() {
    asm volatile("cp.async.wait_group %0;\n" :: "n"(N));
}

// ---------------- weight pre-round (all three weights in one launch) ----------------
__global__ __launch_bounds__(256)
void round3_kernel(const float* __restrict__ wq, const float* __restrict__ wkv,
                   const float* __restrict__ wo, float* __restrict__ out)
{
    int i = blockIdx.x * 256 + threadIdx.x;     // over 1M float4 (4M floats)
    const int Q4 = 1024*1024/4;
    float4 v;
    if (i < Q4)            v = ((const float4*)wq)[i];
    else if (i < 3*Q4)     v = ((const float4*)wkv)[i - Q4];
    else                   v = ((const float4*)wo)[i - 3*Q4];
    float4 o;
    o.x = f2tf32f(v.x); o.y = f2tf32f(v.y); o.z = f2tf32f(v.z); o.w = f2tf32f(v.w);
    ((float4*)out)[i] = o;
}

// ---------------- LayerNorm: one block per row of 1024; ROUND -> tf32 output ----------------
template<bool ROUND>
__global__ __launch_bounds__(256)
void ln_kernel(const float* __restrict__ x, const float* __restrict__ g,
               const float* __restrict__ bb, float* __restrict__ y)
{
    int row = blockIdx.x;
    int t   = threadIdx.x;
    const float4* xr = (const float4*)(x + (size_t)row * DIMC);
    float4 v = xr[t];
    float s1 = v.x + v.y + v.z + v.w;
    float s2 = v.x*v.x + v.y*v.y + v.z*v.z + v.w*v.w;
    #pragma unroll
    for (int o = 16; o; o >>= 1) {
        s1 += __shfl_xor_sync(0xffffffffu, s1, o);
        s2 += __shfl_xor_sync(0xffffffffu, s2, o);
    }
    __shared__ float sh1[8], sh2[8];
    int warp = t >> 5, lane = t & 31;
    if (lane == 0) { sh1[warp] = s1; sh2[warp] = s2; }
    __syncthreads();
    if (warp == 0) {
        s1 = (lane < 8) ? sh1[lane] : 0.f;
        s2 = (lane < 8) ? sh2[lane] : 0.f;
        #pragma unroll
        for (int o = 4; o; o >>= 1) {
            s1 += __shfl_xor_sync(0xffffffffu, s1, o);
            s2 += __shfl_xor_sync(0xffffffffu, s2, o);
        }
        if (lane == 0) {
            float mean = s1 * (1.0f / DIMC);
            float var  = s2 * (1.0f / DIMC) - mean * mean;
            sh1[0] = mean;
            sh2[0] = rsqrtf(var + 1e-5f);
        }
    }
    __syncthreads();
    float mean = sh1[0], rstd = sh2[0];
    float4 gv = ((const float4*)g)[t];
    float4 bv = ((const float4*)bb)[t];
    float4 o4;
    o4.x = (v.x - mean) * rstd * gv.x + bv.x;
    o4.y = (v.y - mean) * rstd * gv.y + bv.y;
    o4.z = (v.z - mean) * rstd * gv.z + bv.z;
    o4.w = (v.w - mean) * rstd * gv.w + bv.w;
    if (ROUND) {
        o4.x = f2tf32f(o4.x); o4.y = f2tf32f(o4.y);
        o4.z = f2tf32f(o4.z); o4.w = f2tf32f(o4.w);
    }
    ((float4*)(y + (size_t)row * DIMC))[t] = o4;
}

// ---------------- KV build: normalize K (+k_scale), append null, pad, round ----------------
__global__ __launch_bounds__(256)
void kv_norm_kernel(const float* __restrict__ kvp, const float* __restrict__ nullkv,
                    const float* __restrict__ kscale,
                    float* __restrict__ kout, float* __restrict__ vout)
{
    int w    = (blockIdx.x * 256 + threadIdx.x) >> 5;
    int lane = threadIdx.x & 31;
    if (w >= 64 * FT_) return;
    int bh = w / FT_;
    int t  = w - bh * FT_;
    int b  = bh >> 4, h = bh & 15;
    float k0 = 0.f, k1 = 0.f, v0 = 0.f, v1 = 0.f;
    if (t < T_) {
        const float* src = kvp + (size_t)(b * T_ + t) * (2 * INNER_) + h * 64;
        k0 = src[lane];            k1 = src[lane + 32];
        v0 = src[INNER_ + lane];   v1 = src[INNER_ + lane + 32];
    } else if (t < TK_) {
        k0 = nullkv[lane];         k1 = nullkv[lane + 32];
        v0 = nullkv[64 + lane];    v1 = nullkv[64 + lane + 32];
    }
    float ss = k0*k0 + k1*k1;
    #pragma unroll
    for (int o = 16; o; o >>= 1) ss += __shfl_xor_sync(0xffffffffu, ss, o);
    float inv = 1.0f / fmaxf(sqrtf(ss), 1e-12f);
    size_t o = (size_t)w * 64;
    kout[o + lane]      = f2tf32f(k0 * inv * kscale[lane]);
    kout[o + lane + 32] = f2tf32f(k1 * inv * kscale[lane + 32]);
    vout[o + lane]      = f2tf32f(v0);
    vout[o + lane + 32] = f2tf32f(v1);
}

// ---------------- tensor-core SGEMM (tf32, cp.async 3-stage): C = A @ W ----------------
// R10 winner config: 128 threads, 4 warps (2m x 2n), warp tile 64x64, regs ~238, 2 blk/SM.
#define GA_STRIDE 36
#define GB_STRIDE 136
#define GA_WORDS  (128*GA_STRIDE)
#define GB_WORDS  (32*GB_STRIDE)
#define GSTAGE    (GA_WORDS + GB_WORDS)
#define GEMM_SMEM (3*GSTAGE*4)

__global__ __launch_bounds__(128, 2)
void gemm_tc(const float* __restrict__ A, const float* __restrict__ W,
             float* __restrict__ C, int K, int Nc)
{
    extern __shared__ float sm[];
    unsigned smbase = (unsigned)__cvta_generic_to_shared(sm);
    int tid = threadIdx.x, lane = tid & 31, warp = tid >> 5;
    int la3 = lane & 3, lq = lane >> 2;
    int m0 = blockIdx.y * 128, n0 = blockIdx.x * 128;
    int wm = warp & 1, wn = warp >> 1;
    float c[4][8][4] = {};

    const int kIters = K >> 5;

    auto issue = [&](int buf, int k0) {
        unsigned abase = smbase + 4u * (buf * GSTAGE);
        unsigned bbase = abase + 4u * GA_WORDS;
        #pragma unroll
        for (int i = 0; i < 8; i++) {
            int id = tid + i * 128;
            int r = id >> 3, kq = id & 7;
            cp16(abase + 4u * (r * GA_STRIDE + kq * 4),
                 A + (size_t)(m0 + r) * K + k0 + kq * 4);
        }
        #pragma unroll
        for (int i = 0; i < 8; i++) {
            int id = tid + i * 128;
            int kr = id >> 5, nq = id & 31;
            cp16(bbase + 4u * (kr * GB_STRIDE + nq * 4),
                 W + (size_t)(k0 + kr) * Nc + n0 + nq * 4);
        }
    };

    issue(0, 0); cp_commit();
    issue(1, 32); cp_commit();

    for (int ki = 0; ki < kIters; ki++) {
        if (ki + 1 < kIters) cp_wait<1>(); else cp_wait<0>();
        __syncthreads();
        if (ki + 2 < kIters) { issue((ki + 2) % 3, (ki + 2) << 5); cp_commit(); }

        const unsigned* As = (const unsigned*)(sm + (ki % 3) * GSTAGE);
        const unsigned* Bs = As + GA_WORDS;
        #pragma unroll
        for (int ks = 0; ks < 4; ks++) {
            int kk = ks * 8;
            unsigned af[4][4];
            #pragma unroll
            for (int mt = 0; mt < 4; mt++) {
                int m = wm*64 + mt*16 + lq;
                af[mt][0] = As[m * GA_STRIDE + kk + la3];
                af[mt][1] = As[(m + 8) * GA_STRIDE + kk + la3];
                af[mt][2] = As[m * GA_STRIDE + kk + 4 + la3];
                af[mt][3] = As[(m + 8) * GA_STRIDE + kk + 4 + la3];
            }
            unsigned bf[8][2];
            #pragma unroll
            for (int nt = 0; nt < 8; nt++) {
                int n = wn*64 + nt*8 + lq;
                bf[nt][0] = Bs[(kk + la3) * GB_STRIDE + n];
                bf[nt][1] = Bs[(kk + 4 + la3) * GB_STRIDE + n];
            }
            #pragma unroll
            for (int mt = 0; mt < 4; mt++)
                #pragma unroll
                for (int nt = 0; nt < 8; nt++)
                    mma_tf32(c[mt][nt], af[mt], bf[nt]);
        }
    }

    #pragma unroll
    for (int mt = 0; mt < 4; mt++) {
        int row = m0 + wm*64 + mt*16 + lq;
        #pragma unroll
        for (int nt = 0; nt < 8; nt++) {
            int col = n0 + wn*64 + nt*8 + 2*la3;
            *(float2*)&C[(size_t)row * Nc + col]       = make_float2(c[mt][nt][0], c[mt][nt][1]);
            *(float2*)&C[(size_t)(row + 8) * Nc + col] = make_float2(c[mt][nt][2], c[mt][nt][3]);
        }
    }
}

// ================== fused flash attention v5 (tf32, scalar null token) ==================
#define FB_TILE (64*68)
#define FLASH_SMEM (4*FB_TILE*4)

__global__ __launch_bounds__(128, 3)
void flash_kernel(const float* __restrict__ qv, const float* __restrict__ kk,
                  const float* __restrict__ vv, const float* __restrict__ qscale,
                  float* __restrict__ O)
{
    extern __shared__ unsigned fsm[];
    unsigned smbase = (unsigned)__cvta_generic_to_shared(fsm);

    int tid = threadIdx.x, lane = tid & 31, warp = tid >> 5;
    int la3 = lane & 3, lq = lane >> 2;
    int bh = blockIdx.y;
    int b = bh >> 4, h = bh & 15;
    int n0 = blockIdx.x * 64;
    const float* qb = qv + (size_t)(b * N_) * INNER_ + h * 64;
    const float* kb = kk + (size_t)bh * FT_ * D_;
    const float* vb = vv + (size_t)bh * FT_ * D_;
    float* Ob = O + (size_t)(b * N_) * INNER_ + h * 64;

    auto issue_kv = [&](int buf, int ch) {
        unsigned kdst = smbase + 4u * (buf * FB_TILE);
        unsigned vdst = smbase + 4u * ((2 + buf) * FB_TILE);
        const float* ksrc = kb + (size_t)ch * 64 * D_;
        const float* vsrc = vb + (size_t)ch * 64 * D_;
        #pragma unroll
        for (int i = 0; i < 8; i++) {
            int id = tid + i * 128;
            int tr = id >> 4, cq = id & 15;
            cp16(kdst + 4u * (tr * 68 + cq * 4), ksrc + tr * D_ + cq * 4);
            cp16(vdst + 4u * (tr * 68 + cq * 4), vsrc + tr * D_ + cq * 4);
        }
    };

    issue_kv(1, 0); cp_commit();

    // ---- stage Q [64 x 64] into Kb0 as [m][d], l2-normalized * q_scale, tf32 ----
    unsigned* Kb0 = fsm;
    #pragma unroll
    for (int i = 0; i < 8; i++) {
        int l = tid + i * 128;
        int m = l >> 4, cq = l & 15;
        float4 v = *(const float4*)&qb[(size_t)(n0 + m) * INNER_ + cq*4];
        float ss = v.x*v.x + v.y*v.y + v.z*v.z + v.w*v.w;
        #pragma unroll
        for (int o = 8; o; o >>= 1) ss += __shfl_xor_sync(0xffffffffu, ss, o);
        float inv = 1.0f / fmaxf(sqrtf(ss), 1e-12f);
        float4 qs = *(const float4*)&qscale[cq*4];
        uint4 qw = make_uint4(f2tf32(v.x * inv * qs.x), f2tf32(v.y * inv * qs.y),
                              f2tf32(v.z * inv * qs.z), f2tf32(v.w * inv * qs.w));
        *(uint4*)&Kb0[m * 68 + cq * 4] = qw;
    }
    __syncthreads();

    int m = warp * 16 + lq;
    unsigned qf[8][4];
    #pragma unroll
    for (int kf = 0; kf < 8; kf++) {
        int ck = kf*8 + la3;
        qf[kf][0] = Kb0[m * 68 + ck];
        qf[kf][1] = Kb0[(m + 8) * 68 + ck];
        qf[kf][2] = Kb0[m * 68 + ck + 4];
        qf[kf][3] = Kb0[(m + 8) * 68 + ck + 4];
    }

    float l_run[2] = {0.f, 0.f};
    float o[8][4] = {};

    int src0 = (lane & ~3) | (la3 >> 1);
    int src1 = src0 + 2;
    bool odd = la3 & 1;

    for (int ch = 0; ch < 4; ch++) {
        int buf = (ch + 1) & 1;
        cp_wait<0>();
        __syncthreads();
        if (ch + 1 < 4) { issue_kv(buf ^ 1, ch + 1); cp_commit(); }

        const unsigned* Ks = fsm + buf * FB_TILE;
        const unsigned* Vs = fsm + (2 + buf) * FB_TILE;

        float s[8][4] = {};
        #pragma unroll
        for (int kf = 0; kf < 8; kf++) {
            int ck = kf*8 + la3;
            unsigned bf[8][2];
            #pragma unroll
            for (int nt = 0; nt < 8; nt++) {
                int t = nt*8 + lq;
                bf[nt][0] = Ks[t * 68 + ck];
                bf[nt][1] = Ks[t * 68 + ck + 4];
            }
            #pragma unroll
            for (int nt = 0; nt < 8; nt++)
                mma_tf32(s[nt], qf[kf], bf[nt]);
        }

        #pragma unroll
        for (int nt = 0; nt < 8; nt++) {
            #pragma unroll
            for (int j = 0; j < 4; j++) {
                float p = __expf(s[nt][j] * 8.0f);
                s[nt][j] = p;
                l_run[j >> 1] += p;
            }
        }

        #pragma unroll
        for (int kt = 0; kt < 8; kt++) {
            float v00 = __shfl_sync(0xffffffffu, s[kt][0], src0);
            float v01 = __shfl_sync(0xffffffffu, s[kt][1], src0);
            float v10 = __shfl_sync(0xffffffffu, s[kt][0], src1);
            float v11 = __shfl_sync(0xffffffffu, s[kt][1], src1);
            float v20 = __shfl_sync(0xffffffffu, s[kt][2], src0);
            float v21 = __shfl_sync(0xffffffffu, s[kt][3], src0);
            float v30 = __shfl_sync(0xffffffffu, s[kt][2], src1);
            float v31 = __shfl_sync(0xffffffffu, s[kt][3], src1);
            unsigned af[4];
            af[0] = f2tf32(odd ? v01 : v00);
            af[1] = f2tf32(odd ? v21 : v20);
            af[2] = f2tf32(odd ? v11 : v10);
            af[3] = f2tf32(odd ? v31 : v30);
            unsigned bf[8][2];
            #pragma unroll
            for (int nt = 0; nt < 8; nt++) {
                int n = nt*8 + lq;
                bf[nt][0] = Vs[(kt*8 + la3) * 68 + n];
                bf[nt][1] = Vs[(kt*8 + 4 + la3) * 68 + n];
            }
            #pragma unroll
            for (int nt = 0; nt < 8; nt++)
                mma_tf32(o[nt], af, bf[nt]);
        }
    }

    // ---- null token (t = 256), scalar path ----
    const float* kn = kb + 256 * D_;
    float s0 = 0.f, s1 = 0.f;
    #pragma unroll
    for (int kf = 0; kf < 8; kf++) {
        float ka = kn[kf*8 + la3];
        float kb2 = kn[kf*8 + la3 + 4];
        s0 += __uint_as_float(qf[kf][0]) * ka + __uint_as_float(qf[kf][2]) * kb2;
        s1 += __uint_as_float(qf[kf][1]) * ka + __uint_as_float(qf[kf][3]) * kb2;
    }
    #pragma unroll
    for (int ox = 1; ox <= 2; ox <<= 1) {
        s0 += __shfl_xor_sync(0xffffffffu, s0, ox);
        s1 += __shfl_xor_sync(0xffffffffu, s1, ox);
    }
    float p0 = __expf(s0 * 8.0f);
    float p1 = __expf(s1 * 8.0f);
    const float* vn = vb + 256 * D_;
    #pragma unroll
    for (int nt = 0; nt < 8; nt++) {
        int cc = nt*8 + 2*la3;
        float va = vn[cc], vb2 = vn[cc + 1];
        o[nt][0] += p0 * va; o[nt][1] += p0 * vb2;
        o[nt][2] += p1 * va; o[nt][3] += p1 * vb2;
    }

    #pragma unroll
    for (int ox = 1; ox <= 2; ox <<= 1) {
        l_run[0] += __shfl_xor_sync(0xffffffffu, l_run[0], ox);
        l_run[1] += __shfl_xor_sync(0xffffffffu, l_run[1], ox);
    }
    float inv0 = 1.0f / (l_run[0] + p0);
    float inv1 = 1.0f / (l_run[1] + p1);
    int rowg = n0 + warp * 16 + lq;
    #pragma unroll
    for (int nt = 0; nt < 8; nt++) {
        int col = nt*8 + 2*la3;
        *(float2*)&Ob[(size_t)rowg * INNER_ + col] =
            make_float2(f2tf32f(o[nt][0]*inv0), f2tf32f(o[nt][1]*inv0));
        *(float2*)&Ob[(size_t)(rowg + 8) * INNER_ + col] =
            make_float2(f2tf32f(o[nt][2]*inv1), f2tf32f(o[nt][3]*inv1));
    }
}

// ---------------- launch (two-stream fork/join inside graph capture) ----------------
extern "C" void kernel_launch(void* const* d_in, const int* in_sizes, int n_in,
                              void* d_out, int out_size)
{
    const float* x      = (const float*)d_in[0];
    const float* ctx    = (const float*)d_in[1];
    const float* Wq     = (const float*)d_in[2];
    const float* Wkv    = (const float*)d_in[3];
    const float* Wo     = (const float*)d_in[4];
    const float* nullkv = (const float*)d_in[5];
    const float* qscale = (const float*)d_in[6];
    const float* kscale = (const float*)d_in[7];
    const float* ln_in_g  = (const float*)d_in[8];
    const float* ln_in_b  = (const float*)d_in[9];
    const float* ln_ctx_g = (const float*)d_in[10];
    const float* ln_ctx_b = (const float*)d_in[11];
    const float* ln_out_g = (const float*)d_in[12];
    const float* ln_out_b = (const float*)d_in[13];
    float* out = (float*)d_out;

    float *p_xn, *p_cn, *p_q, *p_kv, *p_k, *p_v, *p_ao, *p_pr, *p_w;
    cudaGetSymbolAddress((void**)&p_xn, g_xn);
    cudaGetSymbolAddress((void**)&p_cn, g_cn);
    cudaGetSymbolAddress((void**)&p_q,  g_q);
    cudaGetSymbolAddress((void**)&p_kv, g_kv);
    cudaGetSymbolAddress((void**)&p_k,  g_k);
    cudaGetSymbolAddress((void**)&p_v,  g_v);
    cudaGetSymbolAddress((void**)&p_ao, g_ao);
    cudaGetSymbolAddress((void**)&p_pr, g_pr);
    cudaGetSymbolAddress((void**)&p_w,  g_w);

    float* p_wq  = p_w;
    float* p_wkv = p_w + (size_t)1024*1024;
    float* p_wo  = p_w + (size_t)3*1024*1024;

    static cudaStream_t s2 = 0;
    static cudaEvent_t eFork = 0, eRound = 0, eKV = 0;
    static bool init_done = false;
    if (!init_done) {
        cudaFuncSetAttribute(gemm_tc, cudaFuncAttributeMaxDynamicSharedMemorySize, GEMM_SMEM);
        cudaFuncSetAttribute(flash_kernel, cudaFuncAttributeMaxDynamicSharedMemorySize, FLASH_SMEM);
        cudaStreamCreateWithFlags(&s2, cudaStreamNonBlocking);
        cudaEventCreateWithFlags(&eFork,  cudaEventDisableTiming);
        cudaEventCreateWithFlags(&eRound, cudaEventDisableTiming);
        cudaEventCreateWithFlags(&eKV,    cudaEventDisableTiming);
        init_done = true;
    }

    // ---- fork side stream (chain B: weights round + ctx LN + KV proj + kv build) ----
    cudaEventRecord(eFork, 0);
    cudaStreamWaitEvent(s2, eFork, 0);

    // chain B on s2
    round3_kernel<<<4096, 256, 0, s2>>>(Wq, Wkv, Wo, p_w);
    cudaEventRecord(eRound, s2);                       // Wq/Wo ready
    ln_kernel<true><<<ROWS_C, 256, 0, s2>>>(ctx, ln_ctx_g, ln_ctx_b, p_cn);
    gemm_tc<<<dim3(2*INNER_/128, ROWS_C/128), 128, GEMM_SMEM, s2>>>(p_cn, p_wkv, p_kv, DIMC, 2*INNER_);
    kv_norm_kernel<<<(64*FT_)/8, 256, 0, s2>>>(p_kv, nullkv, kscale, p_k, p_v);
    cudaEventRecord(eKV, s2);                          // K/V ready

    // chain A on default stream
    ln_kernel<true><<<ROWS_X, 256>>>(x, ln_in_g, ln_in_b, p_xn);
    cudaStreamWaitEvent(0, eRound, 0);                 // need rounded Wq
    gemm_tc<<<dim3(INNER_/128, ROWS_X/128), 128, GEMM_SMEM>>>(p_xn, p_wq, p_q, DIMC, INNER_);

    // join: flash needs Q (chain A) and K/V (chain B)
    cudaStreamWaitEvent(0, eKV, 0);
    flash_kernel<<<dim3(N_/64, B_*H_), 128, FLASH_SMEM>>>(p_q, p_k, p_v, qscale, p_ao);
    // output projection + final LN
    gemm_tc<<<dim3(DIMC/128, ROWS_X/128), 128, GEMM_SMEM>>>(p_ao, p_wo, p_pr, INNER_, DIMC);
    ln_kernel<false><<<ROWS_X, 256>>>(p_pr, ln_out_g, ln_out_b, out);
}

// round 16
// speedup vs baseline: 1.5080x; 1.5080x over previous
#include <cuda_runtime.h>
#include <math.h>

// ---------------- problem constants ----------------
#define DIMC   1024
#define B_     4
#define N_     4096
#define T_     256
#define H_     16
#define D_     64
#define INNER_ 1024
#define TK_    257       // T + 1 null token
#define FT_    320       // padded kv storage length
#define ROWS_X (B_*N_)   // 16384
#define ROWS_C (B_*T_)   // 1024

// ---------------- device scratch (static, no allocations) ----------------
__device__ float g_xn[(size_t)ROWS_X*DIMC];
__device__ float g_cn[(size_t)ROWS_C*DIMC];
__device__ float g_q [(size_t)ROWS_X*INNER_];
__device__ float g_kv[(size_t)ROWS_C*2*INNER_];
__device__ float g_k [(size_t)64*FT_*D_];     // normalized, tf32-rounded, [bh][t][d]
__device__ float g_v [(size_t)64*FT_*D_];     // tf32-rounded, [bh][t][d]
__device__ float g_ao[(size_t)ROWS_X*INNER_];
__device__ float g_pr[(size_t)ROWS_X*DIMC];
__device__ float g_w [(size_t)4*1024*1024];   // tf32 weights: Wq[0,1M) Wkv[1M,3M) Wo[3M,4M)

// ---------------- tf32 helpers ----------------
__device__ __forceinline__ unsigned f2tf32(float x) {
    unsigned u;
    asm("cvt.rna.tf32.f32 %0, %1;" : "=r"(u) : "f"(x));
    return u;
}
__device__ __forceinline__ float f2tf32f(float x) { return __uint_as_float(f2tf32(x)); }
__device__ __forceinline__ void mma_tf32(float c[4], const unsigned a[4], const unsigned b[2]) {
    asm volatile(
        "mma.sync.aligned.m16n8k8.row.col.f32.tf32.tf32.f32 "
        "{%0,%1,%2,%3}, {%4,%5,%6,%7}, {%8,%9}, {%0,%1,%2,%3};"
        : "+f"(c[0]), "+f"(c[1]), "+f"(c[2]), "+f"(c[3])
        : "r"(a[0]), "r"(a[1]), "r"(a[2]), "r"(a[3]), "r"(b[0]), "r"(b[1]));
}
__device__ __forceinline__ void cp16(unsigned dst, const void* src) {
    asm volatile("cp.async.cg.shared.global [%0], [%1], 16;\n" :: "r"(dst), "l"(src));
}
__device__ __forceinline__ void cp_commit() { asm volatile("cp.async.commit_group;\n"); }
template<int N> __device__ __forceinline__ void cp_wait() {
    asm volatile("cp.async.wait_group %0;\n" :: "n"(N));
}

// ---------------- weight pre-round (all three weights in one launch) ----------------
__global__ __launch_bounds__(256)
void round3_kernel(const float* __restrict__ wq, const float* __restrict__ wkv,
                   const float* __restrict__ wo, float* __restrict__ out)
{
    int i = blockIdx.x * 256 + threadIdx.x;
    const int Q4 = 1024*1024/4;
    float4 v;
    if (i < Q4)            v = ((const float4*)wq)[i];
    else if (i < 3*Q4)     v = ((const float4*)wkv)[i - Q4];
    else                   v = ((const float4*)wo)[i - 3*Q4];
    float4 o;
    o.x = f2tf32f(v.x); o.y = f2tf32f(v.y); o.z = f2tf32f(v.z); o.w = f2tf32f(v.w);
    ((float4*)out)[i] = o;
}

// ---------------- LayerNorm: one block per row of 1024; ROUND -> tf32 output ----------------
template<bool ROUND>
__global__ __launch_bounds__(256)
void ln_kernel(const float* __restrict__ x, const float* __restrict__ g,
               const float* __restrict__ bb, float* __restrict__ y)
{
    int row = blockIdx.x;
    int t   = threadIdx.x;
    const float4* xr = (const float4*)(x + (size_t)row * DIMC);
    float4 v = xr[t];
    float s1 = v.x + v.y + v.z + v.w;
    float s2 = v.x*v.x + v.y*v.y + v.z*v.z + v.w*v.w;
    #pragma unroll
    for (int o = 16; o; o >>= 1) {
        s1 += __shfl_xor_sync(0xffffffffu, s1, o);
        s2 += __shfl_xor_sync(0xffffffffu, s2, o);
    }
    __shared__ float sh1[8], sh2[8];
    int warp = t >> 5, lane = t & 31;
    if (lane == 0) { sh1[warp] = s1; sh2[warp] = s2; }
    __syncthreads();
    if (warp == 0) {
        s1 = (lane < 8) ? sh1[lane] : 0.f;
        s2 = (lane < 8) ? sh2[lane] : 0.f;
        #pragma unroll
        for (int o = 4; o; o >>= 1) {
            s1 += __shfl_xor_sync(0xffffffffu, s1, o);
            s2 += __shfl_xor_sync(0xffffffffu, s2, o);
        }
        if (lane == 0) {
            float mean = s1 * (1.0f / DIMC);
            float var  = s2 * (1.0f / DIMC) - mean * mean;
            sh1[0] = mean;
            sh2[0] = rsqrtf(var + 1e-5f);
        }
    }
    __syncthreads();
    float mean = sh1[0], rstd = sh2[0];
    float4 gv = ((const float4*)g)[t];
    float4 bv = ((const float4*)bb)[t];
    float4 o4;
    o4.x = (v.x - mean) * rstd * gv.x + bv.x;
    o4.y = (v.y - mean) * rstd * gv.y + bv.y;
    o4.z = (v.z - mean) * rstd * gv.z + bv.z;
    o4.w = (v.w - mean) * rstd * gv.w + bv.w;
    if (ROUND) {
        o4.x = f2tf32f(o4.x); o4.y = f2tf32f(o4.y);
        o4.z = f2tf32f(o4.z); o4.w = f2tf32f(o4.w);
    }
    ((float4*)(y + (size_t)row * DIMC))[t] = o4;
}

// ---------------- KV build: normalize K (+k_scale), append null, pad, round ----------------
__global__ __launch_bounds__(256)
void kv_norm_kernel(const float* __restrict__ kvp, const float* __restrict__ nullkv,
                    const float* __restrict__ kscale,
                    float* __restrict__ kout, float* __restrict__ vout)
{
    int w    = (blockIdx.x * 256 + threadIdx.x) >> 5;
    int lane = threadIdx.x & 31;
    if (w >= 64 * FT_) return;
    int bh = w / FT_;
    int t  = w - bh * FT_;
    int b  = bh >> 4, h = bh & 15;
    float k0 = 0.f, k1 = 0.f, v0 = 0.f, v1 = 0.f;
    if (t < T_) {
        const float* src = kvp + (size_t)(b * T_ + t) * (2 * INNER_) + h * 64;
        k0 = src[lane];            k1 = src[lane + 32];
        v0 = src[INNER_ + lane];   v1 = src[INNER_ + lane + 32];
    } else if (t < TK_) {
        k0 = nullkv[lane];         k1 = nullkv[lane + 32];
        v0 = nullkv[64 + lane];    v1 = nullkv[64 + lane + 32];
    }
    float ss = k0*k0 + k1*k1;
    #pragma unroll
    for (int o = 16; o; o >>= 1) ss += __shfl_xor_sync(0xffffffffu, ss, o);
    float inv = 1.0f / fmaxf(sqrtf(ss), 1e-12f);
    size_t o = (size_t)w * 64;
    kout[o + lane]      = f2tf32f(k0 * inv * kscale[lane]);
    kout[o + lane + 32] = f2tf32f(k1 * inv * kscale[lane + 32]);
    vout[o + lane]      = f2tf32f(v0);
    vout[o + lane + 32] = f2tf32f(v1);
}

// ---------------- tensor-core SGEMM (tf32, cp.async 3-stage): C = A @ W ----------------
// R10 winner config: 128 threads, 4 warps (2m x 2n), warp tile 64x64, regs ~238, 2 blk/SM.
#define GA_STRIDE 36
#define GB_STRIDE 136
#define GA_WORDS  (128*GA_STRIDE)
#define GB_WORDS  (32*GB_STRIDE)
#define GSTAGE    (GA_WORDS + GB_WORDS)
#define GEMM_SMEM (3*GSTAGE*4)

__global__ __launch_bounds__(128, 2)
void gemm_tc(const float* __restrict__ A, const float* __restrict__ W,
             float* __restrict__ C, int K, int Nc)
{
    extern __shared__ float sm[];
    unsigned smbase = (unsigned)__cvta_generic_to_shared(sm);
    int tid = threadIdx.x, lane = tid & 31, warp = tid >> 5;
    int la3 = lane & 3, lq = lane >> 2;
    int m0 = blockIdx.y * 128, n0 = blockIdx.x * 128;
    int wm = warp & 1, wn = warp >> 1;
    float c[4][8][4] = {};

    const int kIters = K >> 5;

    auto issue = [&](int buf, int k0) {
        unsigned abase = smbase + 4u * (buf * GSTAGE);
        unsigned bbase = abase + 4u * GA_WORDS;
        #pragma unroll
        for (int i = 0; i < 8; i++) {
            int id = tid + i * 128;
            int r = id >> 3, kq = id & 7;
            cp16(abase + 4u * (r * GA_STRIDE + kq * 4),
                 A + (size_t)(m0 + r) * K + k0 + kq * 4);
        }
        #pragma unroll
        for (int i = 0; i < 8; i++) {
            int id = tid + i * 128;
            int kr = id >> 5, nq = id & 31;
            cp16(bbase + 4u * (kr * GB_STRIDE + nq * 4),
                 W + (size_t)(k0 + kr) * Nc + n0 + nq * 4);
        }
    };

    issue(0, 0); cp_commit();
    issue(1, 32); cp_commit();

    for (int ki = 0; ki < kIters; ki++) {
        if (ki + 1 < kIters) cp_wait<1>(); else cp_wait<0>();
        __syncthreads();
        if (ki + 2 < kIters) { issue((ki + 2) % 3, (ki + 2) << 5); cp_commit(); }

        const unsigned* As = (const unsigned*)(sm + (ki % 3) * GSTAGE);
        const unsigned* Bs = As + GA_WORDS;
        #pragma unroll
        for (int ks = 0; ks < 4; ks++) {
            int kk = ks * 8;
            unsigned af[4][4];
            #pragma unroll
            for (int mt = 0; mt < 4; mt++) {
                int m = wm*64 + mt*16 + lq;
                af[mt][0] = As[m * GA_STRIDE + kk + la3];
                af[mt][1] = As[(m + 8) * GA_STRIDE + kk + la3];
                af[mt][2] = As[m * GA_STRIDE + kk + 4 + la3];
                af[mt][3] = As[(m + 8) * GA_STRIDE + kk + 4 + la3];
            }
            unsigned bf[8][2];
            #pragma unroll
            for (int nt = 0; nt < 8; nt++) {
                int n = wn*64 + nt*8 + lq;
                bf[nt][0] = Bs[(kk + la3) * GB_STRIDE + n];
                bf[nt][1] = Bs[(kk + 4 + la3) * GB_STRIDE + n];
            }
            #pragma unroll
            for (int mt = 0; mt < 4; mt++)
                #pragma unroll
                for (int nt = 0; nt < 8; nt++)
                    mma_tf32(c[mt][nt], af[mt], bf[nt]);
        }
    }

    #pragma unroll
    for (int mt = 0; mt < 4; mt++) {
        int row = m0 + wm*64 + mt*16 + lq;
        #pragma unroll
        for (int nt = 0; nt < 8; nt++) {
            int col = n0 + wn*64 + nt*8 + 2*la3;
            *(float2*)&C[(size_t)row * Nc + col]       = make_float2(c[mt][nt][0], c[mt][nt][1]);
            *(float2*)&C[(size_t)(row + 8) * Nc + col] = make_float2(c[mt][nt][2], c[mt][nt][3]);
        }
    }
}

// ================== fused flash attention v6 (tf32, 128-row Q tile, scalar null) ==================
// Grid: (N_/128, B_*H_). 256 threads = 8 warps; warp w owns rows w*16..w*16+15.
// KV L2 traffic halved vs 64-row tiles. Q stages through Kb0+Kb1 (exactly 128*68 words),
// consumed into registers before chunk 0's cp.async overwrites the region.
#define FB_TILE (64*68)
#define FLASH_SMEM (4*FB_TILE*4)

__global__ __launch_bounds__(256, 2)
void flash_kernel(const float* __restrict__ qv, const float* __restrict__ kk,
                  const float* __restrict__ vv, const float* __restrict__ qscale,
                  float* __restrict__ O)
{
    extern __shared__ unsigned fsm[];
    unsigned smbase = (unsigned)__cvta_generic_to_shared(fsm);

    int tid = threadIdx.x, lane = tid & 31, warp = tid >> 5;
    int la3 = lane & 3, lq = lane >> 2;
    int bh = blockIdx.y;
    int b = bh >> 4, h = bh & 15;
    int n0 = blockIdx.x * 128;
    const float* qb = qv + (size_t)(b * N_) * INNER_ + h * 64;
    const float* kb = kk + (size_t)bh * FT_ * D_;
    const float* vb = vv + (size_t)bh * FT_ * D_;
    float* Ob = O + (size_t)(b * N_) * INNER_ + h * 64;

    auto issue_kv = [&](int buf, int ch) {
        unsigned kdst = smbase + 4u * (buf * FB_TILE);
        unsigned vdst = smbase + 4u * ((2 + buf) * FB_TILE);
        const float* ksrc = kb + (size_t)ch * 64 * D_;
        const float* vsrc = vb + (size_t)ch * 64 * D_;
        #pragma unroll
        for (int i = 0; i < 4; i++) {
            int id = tid + i * 256;
            int tr = id >> 4, cq = id & 15;
            cp16(kdst + 4u * (tr * 68 + cq * 4), ksrc + tr * D_ + cq * 4);
            cp16(vdst + 4u * (tr * 68 + cq * 4), vsrc + tr * D_ + cq * 4);
        }
    };

    // ---- stage Q [128 x 64] into Kb0+Kb1 region as [m][d], normalized * q_scale ----
    #pragma unroll
    for (int i = 0; i < 8; i++) {
        int l = tid + i * 256;           // 2048 float4
        int m = l >> 4, cq = l & 15;     // 16 consecutive lanes share one row
        float4 v = *(const float4*)&qb[(size_t)(n0 + m) * INNER_ + cq*4];
        float ss = v.x*v.x + v.y*v.y + v.z*v.z + v.w*v.w;
        #pragma unroll
        for (int o = 8; o; o >>= 1) ss += __shfl_xor_sync(0xffffffffu, ss, o);
        float inv = 1.0f / fmaxf(sqrtf(ss), 1e-12f);
        float4 qs = *(const float4*)&qscale[cq*4];
        uint4 qw = make_uint4(f2tf32(v.x * inv * qs.x), f2tf32(v.y * inv * qs.y),
                              f2tf32(v.z * inv * qs.z), f2tf32(v.w * inv * qs.w));
        *(uint4*)&fsm[m * 68 + cq * 4] = qw;     // m in [0,128): spans Kb0+Kb1
    }
    __syncthreads();

    int m = warp * 16 + lq;                      // warp row in [0,128)
    unsigned qf[8][4];
    #pragma unroll
    for (int kf = 0; kf < 8; kf++) {
        int ck = kf*8 + la3;
        qf[kf][0] = fsm[m * 68 + ck];
        qf[kf][1] = fsm[(m + 8) * 68 + ck];
        qf[kf][2] = fsm[m * 68 + ck + 4];
        qf[kf][3] = fsm[(m + 8) * 68 + ck + 4];
    }
    __syncthreads();                             // all qf loaded before overwrite

    issue_kv(1, 0); cp_commit();                 // chunk 0 -> buf 1

    float l_run[2] = {0.f, 0.f};
    float o[8][4] = {};

    int src0 = (lane & ~3) | (la3 >> 1);
    int src1 = src0 + 2;
    bool odd = la3 & 1;

    for (int ch = 0; ch < 4; ch++) {
        int buf = (ch + 1) & 1;
        cp_wait<0>();
        __syncthreads();
        if (ch + 1 < 4) { issue_kv(buf ^ 1, ch + 1); cp_commit(); }

        const unsigned* Ks = fsm + buf * FB_TILE;
        const unsigned* Vs = fsm + (2 + buf) * FB_TILE;

        // ---- S = Q K^T (warp: 16 x 64) ----
        float s[8][4] = {};
        #pragma unroll
        for (int kf = 0; kf < 8; kf++) {
            int ck = kf*8 + la3;
            unsigned bf[8][2];
            #pragma unroll
            for (int nt = 0; nt < 8; nt++) {
                int t = nt*8 + lq;
                bf[nt][0] = Ks[t * 68 + ck];
                bf[nt][1] = Ks[t * 68 + ck + 4];
            }
            #pragma unroll
            for (int nt = 0; nt < 8; nt++)
                mma_tf32(s[nt], qf[kf], bf[nt]);
        }

        // ---- p = exp(8*s) (no mask, no max needed) ----
        #pragma unroll
        for (int nt = 0; nt < 8; nt++) {
            #pragma unroll
            for (int j = 0; j < 4; j++) {
                float p = __expf(s[nt][j] * 8.0f);
                s[nt][j] = p;
                l_run[j >> 1] += p;
            }
        }

        // ---- O += P V: permute C-frag -> A-frag via quad shuffles ----
        #pragma unroll
        for (int kt = 0; kt < 8; kt++) {
            float v00 = __shfl_sync(0xffffffffu, s[kt][0], src0);
            float v01 = __shfl_sync(0xffffffffu, s[kt][1], src0);
            float v10 = __shfl_sync(0xffffffffu, s[kt][0], src1);
            float v11 = __shfl_sync(0xffffffffu, s[kt][1], src1);
            float v20 = __shfl_sync(0xffffffffu, s[kt][2], src0);
            float v21 = __shfl_sync(0xffffffffu, s[kt][3], src0);
            float v30 = __shfl_sync(0xffffffffu, s[kt][2], src1);
            float v31 = __shfl_sync(0xffffffffu, s[kt][3], src1);
            unsigned af[4];
            af[0] = f2tf32(odd ? v01 : v00);
            af[1] = f2tf32(odd ? v21 : v20);
            af[2] = f2tf32(odd ? v11 : v10);
            af[3] = f2tf32(odd ? v31 : v30);
            unsigned bf[8][2];
            #pragma unroll
            for (int nt = 0; nt < 8; nt++) {
                int n = nt*8 + lq;
                bf[nt][0] = Vs[(kt*8 + la3) * 68 + n];
                bf[nt][1] = Vs[(kt*8 + 4 + la3) * 68 + n];
            }
            #pragma unroll
            for (int nt = 0; nt < 8; nt++)
                mma_tf32(o[nt], af, bf[nt]);
        }
    }

    // ---- null token (t = 256), scalar path ----
    const float* kn = kb + 256 * D_;
    float s0 = 0.f, s1 = 0.f;
    #pragma unroll
    for (int kf = 0; kf < 8; kf++) {
        float ka = kn[kf*8 + la3];
        float kb2 = kn[kf*8 + la3 + 4];
        s0 += __uint_as_float(qf[kf][0]) * ka + __uint_as_float(qf[kf][2]) * kb2;
        s1 += __uint_as_float(qf[kf][1]) * ka + __uint_as_float(qf[kf][3]) * kb2;
    }
    #pragma unroll
    for (int ox = 1; ox <= 2; ox <<= 1) {
        s0 += __shfl_xor_sync(0xffffffffu, s0, ox);
        s1 += __shfl_xor_sync(0xffffffffu, s1, ox);
    }
    float p0 = __expf(s0 * 8.0f);
    float p1 = __expf(s1 * 8.0f);
    const float* vn = vb + 256 * D_;
    #pragma unroll
    for (int nt = 0; nt < 8; nt++) {
        int cc = nt*8 + 2*la3;
        float va = vn[cc], vb2 = vn[cc + 1];
        o[nt][0] += p0 * va; o[nt][1] += p0 * vb2;
        o[nt][2] += p1 * va; o[nt][3] += p1 * vb2;
    }

    // ---- row-sum reduce (quad), add null p, scale + write ----
    #pragma unroll
    for (int ox = 1; ox <= 2; ox <<= 1) {
        l_run[0] += __shfl_xor_sync(0xffffffffu, l_run[0], ox);
        l_run[1] += __shfl_xor_sync(0xffffffffu, l_run[1], ox);
    }
    float inv0 = 1.0f / (l_run[0] + p0);
    float inv1 = 1.0f / (l_run[1] + p1);
    int rowg = n0 + warp * 16 + lq;
    #pragma unroll
    for (int nt = 0; nt < 8; nt++) {
        int col = nt*8 + 2*la3;
        *(float2*)&Ob[(size_t)rowg * INNER_ + col] =
            make_float2(f2tf32f(o[nt][0]*inv0), f2tf32f(o[nt][1]*inv0));
        *(float2*)&Ob[(size_t)(rowg + 8) * INNER_ + col] =
            make_float2(f2tf32f(o[nt][2]*inv1), f2tf32f(o[nt][3]*inv1));
    }
}

// ---------------- launch (single stream, R12 order) ----------------
extern "C" void kernel_launch(void* const* d_in, const int* in_sizes, int n_in,
                              void* d_out, int out_size)
{
    const float* x      = (const float*)d_in[0];
    const float* ctx    = (const float*)d_in[1];
    const float* Wq     = (const float*)d_in[2];
    const float* Wkv    = (const float*)d_in[3];
    const float* Wo     = (const float*)d_in[4];
    const float* nullkv = (const float*)d_in[5];
    const float* qscale = (const float*)d_in[6];
    const float* kscale = (const float*)d_in[7];
    const float* ln_in_g  = (const float*)d_in[8];
    const float* ln_in_b  = (const float*)d_in[9];
    const float* ln_ctx_g = (const float*)d_in[10];
    const float* ln_ctx_b = (const float*)d_in[11];
    const float* ln_out_g = (const float*)d_in[12];
    const float* ln_out_b = (const float*)d_in[13];
    float* out = (float*)d_out;

    float *p_xn, *p_cn, *p_q, *p_kv, *p_k, *p_v, *p_ao, *p_pr, *p_w;
    cudaGetSymbolAddress((void**)&p_xn, g_xn);
    cudaGetSymbolAddress((void**)&p_cn, g_cn);
    cudaGetSymbolAddress((void**)&p_q,  g_q);
    cudaGetSymbolAddress((void**)&p_kv, g_kv);
    cudaGetSymbolAddress((void**)&p_k,  g_k);
    cudaGetSymbolAddress((void**)&p_v,  g_v);
    cudaGetSymbolAddress((void**)&p_ao, g_ao);
    cudaGetSymbolAddress((void**)&p_pr, g_pr);
    cudaGetSymbolAddress((void**)&p_w,  g_w);

    float* p_wq  = p_w;
    float* p_wkv = p_w + (size_t)1024*1024;
    float* p_wo  = p_w + (size_t)3*1024*1024;

    cudaFuncSetAttribute(gemm_tc, cudaFuncAttributeMaxDynamicSharedMemorySize, GEMM_SMEM);
    cudaFuncSetAttribute(flash_kernel, cudaFuncAttributeMaxDynamicSharedMemorySize, FLASH_SMEM);

    // 1-2: LayerNorms (tf32-rounded outputs)
    ln_kernel<true><<<ROWS_X, 256>>>(x,   ln_in_g,  ln_in_b,  p_xn);
    ln_kernel<true><<<ROWS_C, 256>>>(ctx, ln_ctx_g, ln_ctx_b, p_cn);
    // 3: round all weights (one launch), 4: Q projection (profiled slot)
    round3_kernel<<<4096, 256>>>(Wq, Wkv, Wo, p_w);
    gemm_tc<<<dim3(INNER_/128, ROWS_X/128), 128, GEMM_SMEM>>>(p_xn, p_wq, p_q, DIMC, INNER_);
    // 5: KV projection
    gemm_tc<<<dim3(2*INNER_/128, ROWS_C/128), 128, GEMM_SMEM>>>(p_cn, p_wkv, p_kv, DIMC, 2*INNER_);
    // 6: K/V build (normalize + null + pad + round), [bh][t][d]
    kv_norm_kernel<<<(64*FT_)/8, 256>>>(p_kv, nullkv, kscale, p_k, p_v);
    // 7: fused attention (128-row Q tiles, 4 chunks + scalar null token)
    flash_kernel<<<dim3(N_/128, B_*H_), 256, FLASH_SMEM>>>(p_q, p_k, p_v, qscale, p_ao);
    // 8: output projection
    gemm_tc<<<dim3(DIMC/128, ROWS_X/128), 128, GEMM_SMEM>>>(p_ao, p_wo, p_pr, INNER_, DIMC);
    // 9: final LN -> d_out (full fp32)
    ln_kernel<false><<<ROWS_X, 256>>>(p_pr, ln_out_g, ln_out_b, out);
}

// round 17
// speedup vs baseline: 1.5545x; 1.0308x over previous
#include <cuda_runtime.h>
#include <math.h>

// ---------------- problem constants ----------------
#define DIMC   1024
#define B_     4
#define N_     4096
#define T_     256
#define H_     16
#define D_     64
#define INNER_ 1024
#define TK_    257       // T + 1 null token
#define FT_    320       // padded kv storage length
#define ROWS_X (B_*N_)   // 16384
#define ROWS_C (B_*T_)   // 1024

// ---------------- device scratch (static, no allocations) ----------------
__device__ float g_xn[(size_t)ROWS_X*DIMC];
__device__ float g_cn[(size_t)ROWS_C*DIMC];
__device__ float g_q [(size_t)ROWS_X*INNER_];
__device__ float g_kv[(size_t)ROWS_C*2*INNER_];
__device__ float g_k [(size_t)64*FT_*D_];     // normalized, tf32-rounded, [bh][t][d]
__device__ float g_v [(size_t)64*FT_*D_];     // tf32-rounded, [bh][t][d]
__device__ float g_ao[(size_t)ROWS_X*INNER_];
__device__ float g_pr[(size_t)ROWS_X*DIMC];
__device__ float g_w [(size_t)4*1024*1024];   // tf32 weights: Wq[0,1M) Wkv[1M,3M) Wo[3M,4M)

// ---------------- tf32 helpers ----------------
__device__ __forceinline__ unsigned f2tf32(float x) {
    unsigned u;
    asm("cvt.rna.tf32.f32 %0, %1;" : "=r"(u) : "f"(x));
    return u;
}
__device__ __forceinline__ float f2tf32f(float x) { return __uint_as_float(f2tf32(x)); }
__device__ __forceinline__ void mma_tf32(float c[4], const unsigned a[4], const unsigned b[2]) {
    asm volatile(
        "mma.sync.aligned.m16n8k8.row.col.f32.tf32.tf32.f32 "
        "{%0,%1,%2,%3}, {%4,%5,%6,%7}, {%8,%9}, {%0,%1,%2,%3};"
        : "+f"(c[0]), "+f"(c[1]), "+f"(c[2]), "+f"(c[3])
        : "r"(a[0]), "r"(a[1]), "r"(a[2]), "r"(a[3]), "r"(b[0]), "r"(b[1]));
}
__device__ __forceinline__ void cp16(unsigned dst, const void* src) {
    asm volatile("cp.async.cg.shared.global [%0], [%1], 16;\n" :: "r"(dst), "l"(src));
}
__device__ __forceinline__ void cp_commit() { asm volatile("cp.async.commit_group;\n"); }
template<int N> __device__ __forceinline__ void cp_wait() {
    asm volatile("cp.async.wait_group %0;\n" :: "n"(N));
}
// ldmatrix x4 over 8x8 b32 tiles (tf32 A-frag loader)
__device__ __forceinline__ void ldsm_x4(unsigned a[4], unsigned addr) {
    asm volatile("ldmatrix.sync.aligned.m8n8.x4.shared.b16 {%0,%1,%2,%3}, [%4];"
                 : "=r"(a[0]), "=r"(a[1]), "=r"(a[2]), "=r"(a[3]) : "r"(addr));
}

// ---------------- weight pre-round (all three weights in one launch) ----------------
__global__ __launch_bounds__(256)
void round3_kernel(const float* __restrict__ wq, const float* __restrict__ wkv,
                   const float* __restrict__ wo, float* __restrict__ out)
{
    int i = blockIdx.x * 256 + threadIdx.x;
    const int Q4 = 1024*1024/4;
    float4 v;
    if (i < Q4)            v = ((const float4*)wq)[i];
    else if (i < 3*Q4)     v = ((const float4*)wkv)[i - Q4];
    else                   v = ((const float4*)wo)[i - 3*Q4];
    float4 o;
    o.x = f2tf32f(v.x); o.y = f2tf32f(v.y); o.z = f2tf32f(v.z); o.w = f2tf32f(v.w);
    ((float4*)out)[i] = o;
}

// ---------------- LayerNorm: one block per row of 1024; ROUND -> tf32 output ----------------
template<bool ROUND>
__global__ __launch_bounds__(256)
void ln_kernel(const float* __restrict__ x, const float* __restrict__ g,
               const float* __restrict__ bb, float* __restrict__ y)
{
    int row = blockIdx.x;
    int t   = threadIdx.x;
    const float4* xr = (const float4*)(x + (size_t)row * DIMC);
    float4 v = xr[t];
    float s1 = v.x + v.y + v.z + v.w;
    float s2 = v.x*v.x + v.y*v.y + v.z*v.z + v.w*v.w;
    #pragma unroll
    for (int o = 16; o; o >>= 1) {
        s1 += __shfl_xor_sync(0xffffffffu, s1, o);
        s2 += __shfl_xor_sync(0xffffffffu, s2, o);
    }
    __shared__ float sh1[8], sh2[8];
    int warp = t >> 5, lane = t & 31;
    if (lane == 0) { sh1[warp] = s1; sh2[warp] = s2; }
    __syncthreads();
    if (warp == 0) {
        s1 = (lane < 8) ? sh1[lane] : 0.f;
        s2 = (lane < 8) ? sh2[lane] : 0.f;
        #pragma unroll
        for (int o = 4; o; o >>= 1) {
            s1 += __shfl_xor_sync(0xffffffffu, s1, o);
            s2 += __shfl_xor_sync(0xffffffffu, s2, o);
        }
        if (lane == 0) {
            float mean = s1 * (1.0f / DIMC);
            float var  = s2 * (1.0f / DIMC) - mean * mean;
            sh1[0] = mean;
            sh2[0] = rsqrtf(var + 1e-5f);
        }
    }
    __syncthreads();
    float mean = sh1[0], rstd = sh2[0];
    float4 gv = ((const float4*)g)[t];
    float4 bv = ((const float4*)bb)[t];
    float4 o4;
    o4.x = (v.x - mean) * rstd * gv.x + bv.x;
    o4.y = (v.y - mean) * rstd * gv.y + bv.y;
    o4.z = (v.z - mean) * rstd * gv.z + bv.z;
    o4.w = (v.w - mean) * rstd * gv.w + bv.w;
    if (ROUND) {
        o4.x = f2tf32f(o4.x); o4.y = f2tf32f(o4.y);
        o4.z = f2tf32f(o4.z); o4.w = f2tf32f(o4.w);
    }
    ((float4*)(y + (size_t)row * DIMC))[t] = o4;
}

// ---------------- KV build: normalize K (+k_scale), append null, pad, round ----------------
__global__ __launch_bounds__(256)
void kv_norm_kernel(const float* __restrict__ kvp, const float* __restrict__ nullkv,
                    const float* __restrict__ kscale,
                    float* __restrict__ kout, float* __restrict__ vout)
{
    int w    = (blockIdx.x * 256 + threadIdx.x) >> 5;
    int lane = threadIdx.x & 31;
    if (w >= 64 * FT_) return;
    int bh = w / FT_;
    int t  = w - bh * FT_;
    int b  = bh >> 4, h = bh & 15;
    float k0 = 0.f, k1 = 0.f, v0 = 0.f, v1 = 0.f;
    if (t < T_) {
        const float* src = kvp + (size_t)(b * T_ + t) * (2 * INNER_) + h * 64;
        k0 = src[lane];            k1 = src[lane + 32];
        v0 = src[INNER_ + lane];   v1 = src[INNER_ + lane + 32];
    } else if (t < TK_) {
        k0 = nullkv[lane];         k1 = nullkv[lane + 32];
        v0 = nullkv[64 + lane];    v1 = nullkv[64 + lane + 32];
    }
    float ss = k0*k0 + k1*k1;
    #pragma unroll
    for (int o = 16; o; o >>= 1) ss += __shfl_xor_sync(0xffffffffu, ss, o);
    float inv = 1.0f / fmaxf(sqrtf(ss), 1e-12f);
    size_t o = (size_t)w * 64;
    kout[o + lane]      = f2tf32f(k0 * inv * kscale[lane]);
    kout[o + lane + 32] = f2tf32f(k1 * inv * kscale[lane + 32]);
    vout[o + lane]      = f2tf32f(v0);
    vout[o + lane + 32] = f2tf32f(v1);
}

// ---------------- tensor-core SGEMM (tf32, cp.async 3-stage, LDSM A-frags) ----------------
// R10 winner config + ldmatrix.x4 A-fragment loads (4 LDS.32 -> 1 LDSM per frag).
#define GA_STRIDE 36
#define GB_STRIDE 136
#define GA_WORDS  (128*GA_STRIDE)
#define GB_WORDS  (32*GB_STRIDE)
#define GSTAGE    (GA_WORDS + GB_WORDS)
#define GEMM_SMEM (3*GSTAGE*4)

__global__ __launch_bounds__(128, 2)
void gemm_tc(const float* __restrict__ A, const float* __restrict__ W,
             float* __restrict__ C, int K, int Nc)
{
    extern __shared__ float sm[];
    unsigned smbase = (unsigned)__cvta_generic_to_shared(sm);
    int tid = threadIdx.x, lane = tid & 31, warp = tid >> 5;
    int la3 = lane & 3, lq = lane >> 2;
    int m0 = blockIdx.y * 128, n0 = blockIdx.x * 128;
    int wm = warp & 1, wn = warp >> 1;
    float c[4][8][4] = {};

    const int kIters = K >> 5;

    // per-thread LDSM address component: sub = lane>>3; bit0 -> +8 rows, bit1 -> +4 cols
    int sub = lane >> 3, srow = lane & 7;
    unsigned a_off = 4u * (((unsigned)(srow + (sub & 1) * 8 + wm * 64) * GA_STRIDE)
                           + (unsigned)((sub >> 1) * 4));

    auto issue = [&](int buf, int k0) {
        unsigned abase = smbase + 4u * (buf * GSTAGE);
        unsigned bbase = abase + 4u * GA_WORDS;
        #pragma unroll
        for (int i = 0; i < 8; i++) {
            int id = tid + i * 128;
            int r = id >> 3, kq = id & 7;
            cp16(abase + 4u * (r * GA_STRIDE + kq * 4),
                 A + (size_t)(m0 + r) * K + k0 + kq * 4);
        }
        #pragma unroll
        for (int i = 0; i < 8; i++) {
            int id = tid + i * 128;
            int kr = id >> 5, nq = id & 31;
            cp16(bbase + 4u * (kr * GB_STRIDE + nq * 4),
                 W + (size_t)(k0 + kr) * Nc + n0 + nq * 4);
        }
    };

    issue(0, 0); cp_commit();
    issue(1, 32); cp_commit();

    for (int ki = 0; ki < kIters; ki++) {
        if (ki + 1 < kIters) cp_wait<1>(); else cp_wait<0>();
        __syncthreads();
        if (ki + 2 < kIters) { issue((ki + 2) % 3, (ki + 2) << 5); cp_commit(); }

        unsigned abase = smbase + 4u * ((ki % 3) * GSTAGE);
        unsigned a_t = abase + a_off;
        const unsigned* Bs = (const unsigned*)(sm + (ki % 3) * GSTAGE) + GA_WORDS;
        #pragma unroll
        for (int ks = 0; ks < 4; ks++) {
            int kk = ks * 8;
            unsigned af[4][4];
            #pragma unroll
            for (int mt = 0; mt < 4; mt++)
                ldsm_x4(af[mt], a_t + 4u * (unsigned)(mt * 16 * GA_STRIDE + kk));
            unsigned bf[8][2];
            #pragma unroll
            for (int nt = 0; nt < 8; nt++) {
                int n = wn*64 + nt*8 + lq;
                bf[nt][0] = Bs[(kk + la3) * GB_STRIDE + n];
                bf[nt][1] = Bs[(kk + 4 + la3) * GB_STRIDE + n];
            }
            #pragma unroll
            for (int mt = 0; mt < 4; mt++)
                #pragma unroll
                for (int nt = 0; nt < 8; nt++)
                    mma_tf32(c[mt][nt], af[mt], bf[nt]);
        }
    }

    #pragma unroll
    for (int mt = 0; mt < 4; mt++) {
        int row = m0 + wm*64 + mt*16 + lq;
        #pragma unroll
        for (int nt = 0; nt < 8; nt++) {
            int col = n0 + wn*64 + nt*8 + 2*la3;
            *(float2*)&C[(size_t)row * Nc + col]       = make_float2(c[mt][nt][0], c[mt][nt][1]);
            *(float2*)&C[(size_t)(row + 8) * Nc + col] = make_float2(c[mt][nt][2], c[mt][nt][3]);
        }
    }
}

// ================== fused flash attention v6 (tf32, 128-row Q tile, scalar null) ==================
#define FB_TILE (64*68)
#define FLASH_SMEM (4*FB_TILE*4)

__global__ __launch_bounds__(256, 2)
void flash_kernel(const float* __restrict__ qv, const float* __restrict__ kk,
                  const float* __restrict__ vv, const float* __restrict__ qscale,
                  float* __restrict__ O)
{
    extern __shared__ unsigned fsm[];
    unsigned smbase = (unsigned)__cvta_generic_to_shared(fsm);

    int tid = threadIdx.x, lane = tid & 31, warp = tid >> 5;
    int la3 = lane & 3, lq = lane >> 2;
    int bh = blockIdx.y;
    int b = bh >> 4, h = bh & 15;
    int n0 = blockIdx.x * 128;
    const float* qb = qv + (size_t)(b * N_) * INNER_ + h * 64;
    const float* kb = kk + (size_t)bh * FT_ * D_;
    const float* vb = vv + (size_t)bh * FT_ * D_;
    float* Ob = O + (size_t)(b * N_) * INNER_ + h * 64;

    auto issue_kv = [&](int buf, int ch) {
        unsigned kdst = smbase + 4u * (buf * FB_TILE);
        unsigned vdst = smbase + 4u * ((2 + buf) * FB_TILE);
        const float* ksrc = kb + (size_t)ch * 64 * D_;
        const float* vsrc = vb + (size_t)ch * 64 * D_;
        #pragma unroll
        for (int i = 0; i < 4; i++) {
            int id = tid + i * 256;
            int tr = id >> 4, cq = id & 15;
            cp16(kdst + 4u * (tr * 68 + cq * 4), ksrc + tr * D_ + cq * 4);
            cp16(vdst + 4u * (tr * 68 + cq * 4), vsrc + tr * D_ + cq * 4);
        }
    };

    // ---- stage Q [128 x 64] into Kb0+Kb1 region as [m][d], normalized * q_scale ----
    #pragma unroll
    for (int i = 0; i < 8; i++) {
        int l = tid + i * 256;
        int m = l >> 4, cq = l & 15;
        float4 v = *(const float4*)&qb[(size_t)(n0 + m) * INNER_ + cq*4];
        float ss = v.x*v.x + v.y*v.y + v.z*v.z + v.w*v.w;
        #pragma unroll
        for (int o = 8; o; o >>= 1) ss += __shfl_xor_sync(0xffffffffu, ss, o);
        float inv = 1.0f / fmaxf(sqrtf(ss), 1e-12f);
        float4 qs = *(const float4*)&qscale[cq*4];
        uint4 qw = make_uint4(f2tf32(v.x * inv * qs.x), f2tf32(v.y * inv * qs.y),
                              f2tf32(v.z * inv * qs.z), f2tf32(v.w * inv * qs.w));
        *(uint4*)&fsm[m * 68 + cq * 4] = qw;
    }
    __syncthreads();

    int m = warp * 16 + lq;
    unsigned qf[8][4];
    #pragma unroll
    for (int kf = 0; kf < 8; kf++) {
        int ck = kf*8 + la3;
        qf[kf][0] = fsm[m * 68 + ck];
        qf[kf][1] = fsm[(m + 8) * 68 + ck];
        qf[kf][2] = fsm[m * 68 + ck + 4];
        qf[kf][3] = fsm[(m + 8) * 68 + ck + 4];
    }
    __syncthreads();

    issue_kv(1, 0); cp_commit();

    float l_run[2] = {0.f, 0.f};
    float o[8][4] = {};

    int src0 = (lane & ~3) | (la3 >> 1);
    int src1 = src0 + 2;
    bool odd = la3 & 1;

    for (int ch = 0; ch < 4; ch++) {
        int buf = (ch + 1) & 1;
        cp_wait<0>();
        __syncthreads();
        if (ch + 1 < 4) { issue_kv(buf ^ 1, ch + 1); cp_commit(); }

        const unsigned* Ks = fsm + buf * FB_TILE;
        const unsigned* Vs = fsm + (2 + buf) * FB_TILE;

        float s[8][4] = {};
        #pragma unroll
        for (int kf = 0; kf < 8; kf++) {
            int ck = kf*8 + la3;
            unsigned bf[8][2];
            #pragma unroll
            for (int nt = 0; nt < 8; nt++) {
                int t = nt*8 + lq;
                bf[nt][0] = Ks[t * 68 + ck];
                bf[nt][1] = Ks[t * 68 + ck + 4];
            }
            #pragma unroll
            for (int nt = 0; nt < 8; nt++)
                mma_tf32(s[nt], qf[kf], bf[nt]);
        }

        #pragma unroll
        for (int nt = 0; nt < 8; nt++) {
            #pragma unroll
            for (int j = 0; j < 4; j++) {
                float p = __expf(s[nt][j] * 8.0f);
                s[nt][j] = p;
                l_run[j >> 1] += p;
            }
        }

        #pragma unroll
        for (int kt = 0; kt < 8; kt++) {
            float v00 = __shfl_sync(0xffffffffu, s[kt][0], src0);
            float v01 = __shfl_sync(0xffffffffu, s[kt][1], src0);
            float v10 = __shfl_sync(0xffffffffu, s[kt][0], src1);
            float v11 = __shfl_sync(0xffffffffu, s[kt][1], src1);
            float v20 = __shfl_sync(0xffffffffu, s[kt][2], src0);
            float v21 = __shfl_sync(0xffffffffu, s[kt][3], src0);
            float v30 = __shfl_sync(0xffffffffu, s[kt][2], src1);
            float v31 = __shfl_sync(0xffffffffu, s[kt][3], src1);
            unsigned af[4];
            af[0] = f2tf32(odd ? v01 : v00);
            af[1] = f2tf32(odd ? v21 : v20);
            af[2] = f2tf32(odd ? v11 : v10);
            af[3] = f2tf32(odd ? v31 : v30);
            unsigned bf[8][2];
            #pragma unroll
            for (int nt = 0; nt < 8; nt++) {
                int n = nt*8 + lq;
                bf[nt][0] = Vs[(kt*8 + la3) * 68 + n];
                bf[nt][1] = Vs[(kt*8 + 4 + la3) * 68 + n];
            }
            #pragma unroll
            for (int nt = 0; nt < 8; nt++)
                mma_tf32(o[nt], af, bf[nt]);
        }
    }

    // ---- null token (t = 256), scalar path ----
    const float* kn = kb + 256 * D_;
    float s0 = 0.f, s1 = 0.f;
    #pragma unroll
    for (int kf = 0; kf < 8; kf++) {
        float ka = kn[kf*8 + la3];
        float kb2 = kn[kf*8 + la3 + 4];
        s0 += __uint_as_float(qf[kf][0]) * ka + __uint_as_float(qf[kf][2]) * kb2;
        s1 += __uint_as_float(qf[kf][1]) * ka + __uint_as_float(qf[kf][3]) * kb2;
    }
    #pragma unroll
    for (int ox = 1; ox <= 2; ox <<= 1) {
        s0 += __shfl_xor_sync(0xffffffffu, s0, ox);
        s1 += __shfl_xor_sync(0xffffffffu, s1, ox);
    }
    float p0 = __expf(s0 * 8.0f);
    float p1 = __expf(s1 * 8.0f);
    const float* vn = vb + 256 * D_;
    #pragma unroll
    for (int nt = 0; nt < 8; nt++) {
        int cc = nt*8 + 2*la3;
        float va = vn[cc], vb2 = vn[cc + 1];
        o[nt][0] += p0 * va; o[nt][1] += p0 * vb2;
        o[nt][2] += p1 * va; o[nt][3] += p1 * vb2;
    }

    #pragma unroll
    for (int ox = 1; ox <= 2; ox <<= 1) {
        l_run[0] += __shfl_xor_sync(0xffffffffu, l_run[0], ox);
        l_run[1] += __shfl_xor_sync(0xffffffffu, l_run[1], ox);
    }
    float inv0 = 1.0f / (l_run[0] + p0);
    float inv1 = 1.0f / (l_run[1] + p1);
    int rowg = n0 + warp * 16 + lq;
    #pragma unroll
    for (int nt = 0; nt < 8; nt++) {
        int col = nt*8 + 2*la3;
        *(float2*)&Ob[(size_t)rowg * INNER_ + col] =
            make_float2(f2tf32f(o[nt][0]*inv0), f2tf32f(o[nt][1]*inv0));
        *(float2*)&Ob[(size_t)(rowg + 8) * INNER_ + col] =
            make_float2(f2tf32f(o[nt][2]*inv1), f2tf32f(o[nt][3]*inv1));
    }
}

// ---------------- launch (single stream) ----------------
extern "C" void kernel_launch(void* const* d_in, const int* in_sizes, int n_in,
                              void* d_out, int out_size)
{
    const float* x      = (const float*)d_in[0];
    const float* ctx    = (const float*)d_in[1];
    const float* Wq     = (const float*)d_in[2];
    const float* Wkv    = (const float*)d_in[3];
    const float* Wo     = (const float*)d_in[4];
    const float* nullkv = (const float*)d_in[5];
    const float* qscale = (const float*)d_in[6];
    const float* kscale = (const float*)d_in[7];
    const float* ln_in_g  = (const float*)d_in[8];
    const float* ln_in_b  = (const float*)d_in[9];
    const float* ln_ctx_g = (const float*)d_in[10];
    const float* ln_ctx_b = (const float*)d_in[11];
    const float* ln_out_g = (const float*)d_in[12];
    const float* ln_out_b = (const float*)d_in[13];
    float* out = (float*)d_out;

    float *p_xn, *p_cn, *p_q, *p_kv, *p_k, *p_v, *p_ao, *p_pr, *p_w;
    cudaGetSymbolAddress((void**)&p_xn, g_xn);
    cudaGetSymbolAddress((void**)&p_cn, g_cn);
    cudaGetSymbolAddress((void**)&p_q,  g_q);
    cudaGetSymbolAddress((void**)&p_kv, g_kv);
    cudaGetSymbolAddress((void**)&p_k,  g_k);
    cudaGetSymbolAddress((void**)&p_v,  g_v);
    cudaGetSymbolAddress((void**)&p_ao, g_ao);
    cudaGetSymbolAddress((void**)&p_pr, g_pr);
    cudaGetSymbolAddress((void**)&p_w,  g_w);

    float* p_wq  = p_w;
    float* p_wkv = p_w + (size_t)1024*1024;
    float* p_wo  = p_w + (size_t)3*1024*1024;

    cudaFuncSetAttribute(gemm_tc, cudaFuncAttributeMaxDynamicSharedMemorySize, GEMM_SMEM);
    cudaFuncSetAttribute(flash_kernel, cudaFuncAttributeMaxDynamicSharedMemorySize, FLASH_SMEM);

    // 1-2: LayerNorms (tf32-rounded outputs)
    ln_kernel<true><<<ROWS_X, 256>>>(x,   ln_in_g,  ln_in_b,  p_xn);
    ln_kernel<true><<<ROWS_C, 256>>>(ctx, ln_ctx_g, ln_ctx_b, p_cn);
    // 3: round all weights (one launch), 4: Q projection (profiled slot)
    round3_kernel<<<4096, 256>>>(Wq, Wkv, Wo, p_w);
    gemm_tc<<<dim3(INNER_/128, ROWS_X/128), 128, GEMM_SMEM>>>(p_xn, p_wq, p_q, DIMC, INNER_);
    // 5: KV projection
    gemm_tc<<<dim3(2*INNER_/128, ROWS_C/128), 128, GEMM_SMEM>>>(p_cn, p_wkv, p_kv, DIMC, 2*INNER_);
    // 6: K/V build (normalize + null + pad + round), [bh][t][d]
    kv_norm_kernel<<<(64*FT_)/8, 256>>>(p_kv, nullkv, kscale, p_k, p_v);
    // 7: fused attention (128-row Q tiles, 4 chunks + scalar null token)
    flash_kernel<<<dim3(N_/128, B_*H_), 256, FLASH_SMEM>>>(p_q, p_k, p_v, qscale, p_ao);
    // 8: output projection
    gemm_tc<<<dim3(DIMC/128, ROWS_X/128), 128, GEMM_SMEM>>>(p_ao, p_wo, p_pr, INNER_, DIMC);
    // 9: final LN -> d_out (full fp32)
    ln_kernel<false><<<ROWS_X, 256>>>(p_pr, ln_out_g, ln_out_b, out);
}